// round 1
// baseline (speedup 1.0000x reference)
#include <cuda_runtime.h>
#include <cstdint>

// Problem constants (match reference)
#define F_DIM   48
#define CHUNKS  12          // 48 floats = 12 float4 per edge

// ---------------------------------------------------------------------------
// Kernel 1: zero the output (harness poisons d_out to 0xAA)
// ---------------------------------------------------------------------------
__global__ void zero_kernel(float4* __restrict__ out, int n4) {
    int i = blockIdx.x * blockDim.x + threadIdx.x;
    if (i < n4) out[i] = make_float4(0.f, 0.f, 0.f, 0.f);
}

// ---------------------------------------------------------------------------
// Kernel 2: fused gather * val * w  ->  vector red scatter-add
// Each edge is handled by 12 consecutive threads, one float4 chunk each.
// z[row, 4c:4c+4] += val * x[col, 4c:4c+4] * w[4c:4c+4]
// ---------------------------------------------------------------------------
__global__ void gcn_scatter_kernel(const float* __restrict__ x,
                                   const float* __restrict__ w,
                                   const int*   __restrict__ rows,
                                   const int*   __restrict__ cols,
                                   const float* __restrict__ vals,
                                   float*       __restrict__ out,
                                   int nE) {
    int gid = blockIdx.x * blockDim.x + threadIdx.x;
    int e = gid / CHUNKS;
    int c = gid - e * CHUNKS;
    if (e >= nE) return;

    int   row = __ldg(rows + e);
    int   col = __ldg(cols + e);
    float v   = __ldg(vals + e);

    const float4 xv = *reinterpret_cast<const float4*>(x + (size_t)col * F_DIM + c * 4);
    const float4 wv = *reinterpret_cast<const float4*>(w + c * 4);

    float4 m;
    m.x = v * xv.x * wv.x;
    m.y = v * xv.y * wv.y;
    m.z = v * xv.z * wv.z;
    m.w = v * xv.w * wv.w;

    float* dst = out + (size_t)row * F_DIM + c * 4;
    asm volatile("red.global.add.v4.f32 [%0], {%1, %2, %3, %4};"
                 :: "l"(dst), "f"(m.x), "f"(m.y), "f"(m.z), "f"(m.w)
                 : "memory");
}

// ---------------------------------------------------------------------------
// Launch
// Inputs (metadata order):
//   0: feature_matrix  float32  [1, 100000, 48]
//   1: weights1        float32  [1, 48]
//   2: adj_rows        int32    [1600000]
//   3: adj_cols        int32    [1600000]
//   4: adj_vals        float32  [1600000]
// Output: float32 [100000, 48]
// ---------------------------------------------------------------------------
extern "C" void kernel_launch(void* const* d_in, const int* in_sizes, int n_in,
                              void* d_out, int out_size) {
    const float* x    = (const float*)d_in[0];
    const float* w    = (const float*)d_in[1];
    const int*   rows = (const int*)  d_in[2];
    const int*   cols = (const int*)  d_in[3];
    const float* vals = (const float*)d_in[4];
    float*       out  = (float*)d_out;

    const int nE = in_sizes[2];            // 1,600,000 edges
    const int nOut = out_size;             // 100000 * 48 floats

    // zero out
    {
        int n4 = nOut / 4;
        int threads = 256;
        int blocks = (n4 + threads - 1) / threads;
        zero_kernel<<<blocks, threads>>>((float4*)out, n4);
    }

    // scatter
    {
        long long total = (long long)nE * CHUNKS;   // 19.2M threads
        int threads = 256;
        int blocks = (int)((total + threads - 1) / threads);
        gcn_scatter_kernel<<<blocks, threads>>>(x, w, rows, cols, vals, out, nE);
    }
}